// round 10
// baseline (speedup 1.0000x reference)
#include <cuda_runtime.h>
#include <cuda_fp16.h>
#include <cstdint>

#define NTOK     8192
#define DM       2048
#define DH       2048
#define NEXP     8
#define TOPK     2
#define TASSIGN  (NTOK * TOPK)
#define CAP      2560

#define BM 128
#define BK 32
#define KIT (2048 / BK)        // 64 k-slabs
#define NSTAGE 6
#define STAGE_BYTES 16384      // A 8KB + B 8KB
#define WRAP (NSTAGE * STAGE_BYTES)

// ---------------- scratch (device globals) ----------------
__device__ int    g_counts[NEXP];
__device__ int    g_tok[NEXP * CAP];
__device__ int    g_slot[TASSIGN];
__device__ __half g_x16[(size_t)NTOK * DM];
__device__ __half g_w1t[(size_t)NEXP * DM * DH];
__device__ __half g_w2t[(size_t)NEXP * DH * DM];
__device__ __half g_w3t[(size_t)NEXP * DM * DH];
__device__ __half g_h  [(size_t)NEXP * CAP * DH];
__device__ float  g_y  [(size_t)NEXP * CAP * DM];

// ---------------- helpers ----------------
__device__ __forceinline__ uint32_t smem_u32(const void* p) {
    uint32_t a;
    asm("{ .reg .u64 t; cvta.to.shared.u64 t, %1; cvt.u32.u64 %0, t; }" : "=r"(a) : "l"(p));
    return a;
}
__device__ __forceinline__ uint32_t swz64(uint32_t o) { return o ^ ((o >> 3) & 0x30); }

__device__ __forceinline__ void cpasync16(uint32_t dst, const void* src) {
    asm volatile("cp.async.cg.shared.global [%0], [%1], 16;" :: "r"(dst), "l"(src) : "memory");
}
__device__ __forceinline__ void cp_commit() {
    asm volatile("cp.async.commit_group;" ::: "memory");
}
__device__ __forceinline__ void cp_wait1() {
    asm volatile("cp.async.wait_group 1;" ::: "memory");
}

__device__ __forceinline__ void ldsm4(uint32_t& r0, uint32_t& r1, uint32_t& r2, uint32_t& r3,
                                      uint32_t addr) {
    asm volatile("ldmatrix.sync.aligned.m8n8.x4.shared.b16 {%0,%1,%2,%3}, [%4];"
                 : "=r"(r0), "=r"(r1), "=r"(r2), "=r"(r3) : "r"(addr));
}

__device__ __forceinline__ void mma16816(float* d, const uint32_t* a, const uint32_t* b) {
    asm volatile(
        "mma.sync.aligned.m16n8k16.row.col.f32.f16.f16.f32 "
        "{%0,%1,%2,%3}, {%4,%5,%6,%7}, {%8,%9}, {%0,%1,%2,%3};"
        : "+f"(d[0]), "+f"(d[1]), "+f"(d[2]), "+f"(d[3])
        : "r"(a[0]), "r"(a[1]), "r"(a[2]), "r"(a[3]), "r"(b[0]), "r"(b[1]));
}

// ---------------- routing ----------------
__global__ void route_kernel(const int* __restrict__ idx) {
    int w    = threadIdx.x >> 5;
    int lane = threadIdx.x & 31;
    if (w >= NEXP) return;
    int base = 0;
    for (int t0 = 0; t0 < TASSIGN; t0 += 32) {
        int t = t0 + lane;
        int e = idx[t];
        bool m = (e == w);
        unsigned mask = __ballot_sync(0xffffffffu, m);
        if (m) {
            int rank = base + __popc(mask & ((1u << lane) - 1u));
            int slot = -1;
            if (rank < CAP) {
                slot = w * CAP + rank;
                g_tok[slot] = t / TOPK;
            }
            g_slot[t] = slot;
        }
        base += __popc(mask);
    }
    if (lane == 0) g_counts[w] = base;
}

// ---------------- x convert: f32 -> fp16 ----------------
__global__ void xcvt_kernel(const float* __restrict__ x) {
    size_t i = (size_t)blockIdx.x * blockDim.x + threadIdx.x;
    g_x16[i] = __float2half_rn(x[i]);
}

// ---------------- weight transpose + fp16 convert (all 3 weights) ----------------
__global__ void wprep_kernel(const float* __restrict__ w1,
                             const float* __restrict__ w2,
                             const float* __restrict__ w3) {
    __shared__ float t[32][33];
    int z  = blockIdx.z;
    int e  = z & 7;
    int T  = z >> 3;                       // 0: w1, 1: w2, 2: w3
    const float* w = (T == 0) ? w1 : (T == 1) ? w2 : w3;
    __half* dst    = (T == 0) ? g_w1t : (T == 1) ? g_w2t : g_w3t;
    int d0 = blockIdx.y * 32, h0 = blockIdx.x * 32;
    int tx = threadIdx.x, ty = threadIdx.y;
    const float* src = w + (size_t)e * DM * DH;
#pragma unroll
    for (int i = 0; i < 32; i += 8)
        t[ty + i][tx] = src[(size_t)(d0 + ty + i) * DH + h0 + tx];
    __syncthreads();
#pragma unroll
    for (int i = 0; i < 32; i += 8) {
        float v = t[tx][ty + i];
        size_t o = (size_t)e * DM * DH + (size_t)(h0 + ty + i) * DM + d0 + tx;
        dst[o] = __float2half_rn(v);
    }
}

// ---------------- HMMA GEMM (fp16, 6-stage ring, barrier per 2 slabs) ----------------
// Stage: [A 8KB][B 8KB]; both tiles 128 rows x 64B (32 halves), SW64 swizzle.
// MODE 1: fused x@w1 / x@w3 + SwiGLU -> g_h (CTA: 128 M x 64 N of each mat)
// MODE 2: h@w2 -> g_y                (CTA: 128 M x 128 N)
template <int MODE>
__global__ __launch_bounds__(256, 2) void hmma_gemm_kernel() {
    const int e = blockIdx.z;
    int cnt = g_counts[e];
    if (cnt > CAP) cnt = CAP;
    const int m0 = blockIdx.y * BM;
    if (m0 >= cnt) return;
    const int n0 = blockIdx.x * ((MODE == 1) ? 64 : 128);

    extern __shared__ __align__(1024) char smem[];
    uint32_t sb = smem_u32(smem);

    const int tid  = threadIdx.x;
    const int lane = tid & 31;
    const int wid  = tid >> 5;

    // ---- A cp.async: rows rA0 (0..63) and rA1 (64..127), 16B chunk (tid&3) ----
    const int rA0 = tid >> 2;
    const int rA1 = rA0 + 64;
    const int cA  = (tid & 3) * 8;      // halves
    const __half* paj[2];
    if (MODE == 1) {
        paj[0] = g_x16 + (size_t)g_tok[e * CAP + m0 + rA0] * DM + cA;
        paj[1] = g_x16 + (size_t)g_tok[e * CAP + m0 + rA1] * DM + cA;
    } else {
        paj[0] = g_h + ((size_t)e * CAP + m0 + rA0) * DH + cA;
        paj[1] = g_h + ((size_t)e * CAP + m0 + rA1) * DH + cA;
    }
    uint32_t soA[2];
    soA[0] = sb + swz64((uint32_t)(rA0 * 64 + (tid & 3) * 16));
    soA[1] = sb + swz64((uint32_t)(rA1 * 64 + (tid & 3) * 16));

    const __half* pbj[2];
    {
        int rB[2] = {rA0, rA1};
#pragma unroll
        for (int j = 0; j < 2; j++) {
            int rb = rB[j];
            if (MODE == 1) {
                if (rb < 64) pbj[j] = g_w1t + ((size_t)e * DH + n0 + rb) * DM + cA;
                else         pbj[j] = g_w3t + ((size_t)e * DH + n0 + rb - 64) * DM + cA;
            } else {
                pbj[j] = g_w2t + ((size_t)e * DM + n0 + rb) * DH + cA;
            }
        }
    }
    uint32_t soB[2];
    soB[0] = sb + 8192 + swz64((uint32_t)(rA0 * 64 + (tid & 3) * 16));
    soB[1] = sb + 8192 + swz64((uint32_t)(rA1 * 64 + (tid & 3) * 16));

    // ---- warp tiling ----
    int wm, wn, mat;
    if (MODE == 1) { wm = wid & 1; wn = (wid >> 1) & 1; mat = wid >> 2; }
    else           { wm = wid & 1; wn = wid >> 1;       mat = 0; }
    const int mbase = wm * 64;
    const int nbB   = (MODE == 1) ? (mat * 64 + wn * 32) : (wn * 32);

    const int lrow = lane & 15;
    const int lkb  = (lane & 16) ? 16 : 0;

    // ---- fully precomputed LDSM base addresses (chunk0 and chunk1 variants) ----
    uint32_t baseA[4], baseAx[4];
#pragma unroll
    for (int mi = 0; mi < 4; mi++) {
        uint32_t pre = (uint32_t)((mbase + mi * 16 + lrow) * 64 + lkb);
        baseA[mi]  = sb + swz64(pre);
        baseAx[mi] = sb + swz64(pre ^ 32u);
    }
    uint32_t baseB[2], baseBx[2];
#pragma unroll
    for (int g = 0; g < 2; g++) {
        uint32_t pre = (uint32_t)((nbB + g * 16 + lrow) * 64 + lkb);
        baseB[g]  = sb + 8192 + swz64(pre);
        baseBx[g] = sb + 8192 + swz64(pre ^ 32u);
    }

    float acc[4][4][4];
#pragma unroll
    for (int mi = 0; mi < 4; mi++)
#pragma unroll
        for (int ni = 0; ni < 4; ni++)
#pragma unroll
            for (int q = 0; q < 4; q++) acc[mi][ni][q] = 0.f;

    // ---- prologue: slabs 0..3 into stages 0..3, two groups of 2 slabs ----
#pragma unroll
    for (int gidx = 0; gidx < 2; gidx++) {
#pragma unroll
        for (int j = 0; j < 2; j++) {
            int sl = gidx * 2 + j;
            uint32_t o = sl * STAGE_BYTES;
            int k0 = sl * BK;
            cpasync16(soA[0] + o, paj[0] + k0);
            cpasync16(soA[1] + o, paj[1] + k0);
            cpasync16(soB[0] + o, pbj[0] + k0);
            cpasync16(soB[1] + o, pbj[1] + k0);
        }
        cp_commit();
    }
    paj[0] += 4 * BK;  paj[1] += 4 * BK;
    pbj[0] += 4 * BK;  pbj[1] += 4 * BK;

    // ---- main loop: 2 slabs per iteration, 1 barrier/wait per iteration ----
    uint32_t roff = 0;                       // stage offset of slab 2*it
    uint32_t woff = 4 * STAGE_BYTES;         // stage offset for prefetch pair
#pragma unroll 1
    for (int it = 0; it < KIT / 2; it++) {
        cp_wait1();
        __syncthreads();

        if (it < KIT / 2 - 2) {              // prefetch slabs 2it+4, 2it+5
            uint32_t w2o = woff + STAGE_BYTES;
            cpasync16(soA[0] + woff, paj[0]);
            cpasync16(soA[1] + woff, paj[1]);
            cpasync16(soB[0] + woff, pbj[0]);
            cpasync16(soB[1] + woff, pbj[1]);
            cpasync16(soA[0] + w2o, paj[0] + BK);
            cpasync16(soA[1] + w2o, paj[1] + BK);
            cpasync16(soB[0] + w2o, pbj[0] + BK);
            cpasync16(soB[1] + w2o, pbj[1] + BK);
        }
        cp_commit();
        paj[0] += 2 * BK; paj[1] += 2 * BK;
        pbj[0] += 2 * BK; pbj[1] += 2 * BK;

        // ---- compute the 2 resident slabs ----
#pragma unroll
        for (int sl = 0; sl < 2; sl++) {
            const uint32_t so = roff + sl * STAGE_BYTES;

            uint32_t bf[2][4][2];
#pragma unroll
            for (int g = 0; g < 2; g++) {
                uint32_t q0, q1, q2, q3;
                ldsm4(q0, q1, q2, q3, baseB[g] + so);
                bf[0][g * 2 + 0][0] = q0; bf[0][g * 2 + 0][1] = q2;
                bf[0][g * 2 + 1][0] = q1; bf[0][g * 2 + 1][1] = q3;
                ldsm4(q0, q1, q2, q3, baseBx[g] + so);
                bf[1][g * 2 + 0][0] = q0; bf[1][g * 2 + 0][1] = q2;
                bf[1][g * 2 + 1][0] = q1; bf[1][g * 2 + 1][1] = q3;
            }
#pragma unroll
            for (int c = 0; c < 2; c++) {
                uint32_t af[4][4];
#pragma unroll
                for (int mi = 0; mi < 4; mi++)
                    ldsm4(af[mi][0], af[mi][1], af[mi][2], af[mi][3],
                          (c ? baseAx[mi] : baseA[mi]) + so);
#pragma unroll
                for (int mi = 0; mi < 4; mi++)
#pragma unroll
                    for (int ni = 0; ni < 4; ni++)
                        mma16816(acc[mi][ni], af[mi], bf[c][ni]);
            }
        }

        roff += 2 * STAGE_BYTES; if (roff >= WRAP) roff = 0;
        woff += 2 * STAGE_BYTES; if (woff >= WRAP) woff -= WRAP;
    }

    // ---- epilogue ----
    __syncthreads();
    if (MODE == 1) {
        float* fb = (float*)smem;   // 128 x 64 fp32 = 32KB scratch (reuse stages)
        if (mat == 1) {
#pragma unroll
            for (int mi = 0; mi < 4; mi++)
#pragma unroll
                for (int ni = 0; ni < 4; ni++) {
                    int ml = mbase + mi * 16 + (lane >> 2);
                    int nl = wn * 32 + ni * 8 + 2 * (lane & 3);
                    fb[ml * 64 + nl]           = acc[mi][ni][0];
                    fb[ml * 64 + nl + 1]       = acc[mi][ni][1];
                    fb[(ml + 8) * 64 + nl]     = acc[mi][ni][2];
                    fb[(ml + 8) * 64 + nl + 1] = acc[mi][ni][3];
                }
        }
        __syncthreads();
        if (mat == 0) {
#pragma unroll
            for (int mi = 0; mi < 4; mi++)
#pragma unroll
                for (int ni = 0; ni < 4; ni++) {
                    int ml = mbase + mi * 16 + (lane >> 2);
                    int nl = wn * 32 + ni * 8 + 2 * (lane & 3);
#pragma unroll
                    for (int hrow = 0; hrow < 2; hrow++) {
                        int mloc = ml + hrow * 8;
                        int row  = m0 + mloc;
                        if (row >= cnt) continue;
                        float a10 = acc[mi][ni][2 * hrow + 0];
                        float a11 = acc[mi][ni][2 * hrow + 1];
                        float a30 = fb[mloc * 64 + nl];
                        float a31 = fb[mloc * 64 + nl + 1];
                        float h0 = (a10 / (1.f + __expf(-a10))) * a30;
                        float h1 = (a11 / (1.f + __expf(-a11))) * a31;
                        __half2 hp = __floats2half2_rn(h0, h1);
                        size_t o = ((size_t)e * CAP + row) * DH + n0 + nl;
                        *(__half2*)(g_h + o) = hp;
                    }
                }
        }
    } else {
#pragma unroll
        for (int mi = 0; mi < 4; mi++)
#pragma unroll
            for (int ni = 0; ni < 4; ni++) {
                int ml = mbase + mi * 16 + (lane >> 2);
                int nl = nbB + ni * 8 + 2 * (lane & 3);
#pragma unroll
                for (int hrow = 0; hrow < 2; hrow++) {
                    int row = m0 + ml + hrow * 8;
                    if (row >= cnt) continue;
                    float2 v = make_float2(acc[mi][ni][2 * hrow], acc[mi][ni][2 * hrow + 1]);
                    *(float2*)(g_y + ((size_t)e * CAP + row) * DM + n0 + nl) = v;
                }
            }
    }
}

// ---------------- combine ----------------
__global__ void combine_kernel(const float* __restrict__ ew, float* __restrict__ out) {
    int i = blockIdx.x * blockDim.x + threadIdx.x;
    int n = i / (DM / 4);
    int c = (i % (DM / 4)) * 4;
    float4 r = make_float4(0.f, 0.f, 0.f, 0.f);
#pragma unroll
    for (int k = 0; k < TOPK; k++) {
        int slot = g_slot[n * TOPK + k];
        if (slot >= 0) {
            float w = ew[n * TOPK + k];
            float4 v = *(const float4*)(g_y + (size_t)slot * DM + c);
            r.x = fmaf(w, v.x, r.x);
            r.y = fmaf(w, v.y, r.y);
            r.z = fmaf(w, v.z, r.z);
            r.w = fmaf(w, v.w, r.w);
        }
    }
    *(float4*)(out + (size_t)n * DM + c) = r;
}

__global__ void counts_kernel(float* __restrict__ out_tail) {
    if (threadIdx.x < NEXP) out_tail[threadIdx.x] = (float)g_counts[threadIdx.x];
}

// ---------------- launch ----------------
extern "C" void kernel_launch(void* const* d_in, const int* in_sizes, int n_in,
                              void* d_out, int out_size) {
    const float* x  = (const float*)d_in[0];
    const float* ew = (const float*)d_in[1];
    const int*   ix = (const int*)  d_in[2];
    const float* w1 = (const float*)d_in[3];
    const float* w2 = (const float*)d_in[4];
    const float* w3 = (const float*)d_in[5];
    float* out = (float*)d_out;

    const int SMEM = NSTAGE * STAGE_BYTES;   // 98304
    cudaFuncSetAttribute(hmma_gemm_kernel<1>, cudaFuncAttributeMaxDynamicSharedMemorySize, SMEM);
    cudaFuncSetAttribute(hmma_gemm_kernel<2>, cudaFuncAttributeMaxDynamicSharedMemorySize, SMEM);

    route_kernel<<<1, 256>>>(ix);
    xcvt_kernel<<<(NTOK * DM) / 256, 256>>>(x);

    dim3 wg(DH / 32, DM / 32, 3 * NEXP);
    dim3 wb(32, 8);
    wprep_kernel<<<wg, wb>>>(w1, w2, w3);

    dim3 g1(DH / 64, CAP / BM, NEXP);    // 32 x 20 x 8
    hmma_gemm_kernel<1><<<g1, 256, SMEM>>>();

    dim3 g2(DM / 128, CAP / BM, NEXP);   // 16 x 20 x 8
    hmma_gemm_kernel<2><<<g2, 256, SMEM>>>();

    combine_kernel<<<(NTOK * (DM / 4)) / 256, 256>>>(ew, out);

    if (out_size >= NTOK * DM + NEXP)
        counts_kernel<<<1, 32>>>(out + (size_t)NTOK * DM);
}

// round 11
// speedup vs baseline: 1.1220x; 1.1220x over previous
#include <cuda_runtime.h>
#include <cuda_fp16.h>
#include <cstdint>

#define NTOK     8192
#define DM       2048
#define DH       2048
#define NEXP     8
#define TOPK     2
#define TASSIGN  (NTOK * TOPK)
#define CAP      2560

#define BM 128
#define BK 32
#define KIT (2048 / BK)        // 64 k-slabs
#define NSTAGE 4
#define STAGE_BYTES 16384      // A 8KB + B 8KB

// ---------------- scratch (device globals) ----------------
__device__ int    g_counts[NEXP];
__device__ int    g_tok[NEXP * CAP];
__device__ int    g_slot[TASSIGN];
__device__ __half g_x16[(size_t)NTOK * DM];
__device__ __half g_w1t[(size_t)NEXP * DM * DH];
__device__ __half g_w2t[(size_t)NEXP * DH * DM];
__device__ __half g_w3t[(size_t)NEXP * DM * DH];
__device__ __half g_h  [(size_t)NEXP * CAP * DH];
__device__ float  g_y  [(size_t)NEXP * CAP * DM];

// ---------------- helpers ----------------
__device__ __forceinline__ uint32_t smem_u32(const void* p) {
    uint32_t a;
    asm("{ .reg .u64 t; cvta.to.shared.u64 t, %1; cvt.u32.u64 %0, t; }" : "=r"(a) : "l"(p));
    return a;
}
__device__ __forceinline__ uint32_t swz64(uint32_t o) { return o ^ ((o >> 3) & 0x30); }

__device__ __forceinline__ void cpasync16(uint32_t dst, const void* src) {
    asm volatile("cp.async.cg.shared.global [%0], [%1], 16;" :: "r"(dst), "l"(src) : "memory");
}
__device__ __forceinline__ void cp_commit() {
    asm volatile("cp.async.commit_group;" ::: "memory");
}
__device__ __forceinline__ void cp_wait2() {
    asm volatile("cp.async.wait_group 2;" ::: "memory");
}

__device__ __forceinline__ void ldsm4(uint32_t& r0, uint32_t& r1, uint32_t& r2, uint32_t& r3,
                                      uint32_t addr) {
    asm volatile("ldmatrix.sync.aligned.m8n8.x4.shared.b16 {%0,%1,%2,%3}, [%4];"
                 : "=r"(r0), "=r"(r1), "=r"(r2), "=r"(r3) : "r"(addr));
}

__device__ __forceinline__ void mma16816(float* d, const uint32_t* a, const uint32_t* b) {
    asm volatile(
        "mma.sync.aligned.m16n8k16.row.col.f32.f16.f16.f32 "
        "{%0,%1,%2,%3}, {%4,%5,%6,%7}, {%8,%9}, {%0,%1,%2,%3};"
        : "+f"(d[0]), "+f"(d[1]), "+f"(d[2]), "+f"(d[3])
        : "r"(a[0]), "r"(a[1]), "r"(a[2]), "r"(a[3]), "r"(b[0]), "r"(b[1]));
}

// ---------------- routing ----------------
__global__ void route_kernel(const int* __restrict__ idx) {
    int w    = threadIdx.x >> 5;
    int lane = threadIdx.x & 31;
    if (w >= NEXP) return;
    int base = 0;
    for (int t0 = 0; t0 < TASSIGN; t0 += 32) {
        int t = t0 + lane;
        int e = idx[t];
        bool m = (e == w);
        unsigned mask = __ballot_sync(0xffffffffu, m);
        if (m) {
            int rank = base + __popc(mask & ((1u << lane) - 1u));
            int slot = -1;
            if (rank < CAP) {
                slot = w * CAP + rank;
                g_tok[slot] = t / TOPK;
            }
            g_slot[t] = slot;
        }
        base += __popc(mask);
    }
    if (lane == 0) g_counts[w] = base;
}

// ---------------- x convert: f32 -> fp16, vectorized ----------------
__global__ void xcvt_kernel(const float* __restrict__ x) {
    size_t i = ((size_t)blockIdx.x * blockDim.x + threadIdx.x) * 4;
    float4 v = *(const float4*)(x + i);
    __half2 h0 = __floats2half2_rn(v.x, v.y);
    __half2 h1 = __floats2half2_rn(v.z, v.w);
    uint2 pk;
    pk.x = *(uint32_t*)&h0;
    pk.y = *(uint32_t*)&h1;
    *(uint2*)(g_x16 + i) = pk;
}

// ---------------- weight transpose + fp16 convert (vectorized 64x64 tiles) ----------------
__global__ void wprep_kernel(const float* __restrict__ w1,
                             const float* __restrict__ w2,
                             const float* __restrict__ w3) {
    __shared__ float t[64][65];
    int z  = blockIdx.z;
    int e  = z & 7;
    int T  = z >> 3;                       // 0: w1, 1: w2, 2: w3
    const float* w = (T == 0) ? w1 : (T == 1) ? w2 : w3;
    __half* dst    = (T == 0) ? g_w1t : (T == 1) ? g_w2t : g_w3t;
    int d0 = blockIdx.y * 64, h0 = blockIdx.x * 64;
    int tid = threadIdx.x;
    int row = tid >> 4;            // 0..15
    int c4  = (tid & 15) * 4;      // 0..60

    const float* src = w + (size_t)e * DM * DH + (size_t)d0 * DH + h0;
#pragma unroll
    for (int p = 0; p < 4; p++) {
        float4 v = *(const float4*)(src + (size_t)(row + 16 * p) * DH + c4);
        t[row + 16 * p][c4 + 0] = v.x;
        t[row + 16 * p][c4 + 1] = v.y;
        t[row + 16 * p][c4 + 2] = v.z;
        t[row + 16 * p][c4 + 3] = v.w;
    }
    __syncthreads();

    // transposed store: output row oc (h dim), 4 consecutive d columns, uint2
    __half* dbase = dst + (size_t)e * DM * DH + (size_t)h0 * DM + d0;
#pragma unroll
    for (int p = 0; p < 4; p++) {
        int oc = row + 16 * p;             // h-local
        float v0 = t[c4 + 0][oc];
        float v1 = t[c4 + 1][oc];
        float v2 = t[c4 + 2][oc];
        float v3 = t[c4 + 3][oc];
        __half2 h0p = __floats2half2_rn(v0, v1);
        __half2 h1p = __floats2half2_rn(v2, v3);
        uint2 pk;
        pk.x = *(uint32_t*)&h0p;
        pk.y = *(uint32_t*)&h1p;
        *(uint2*)(dbase + (size_t)oc * DM + c4) = pk;
    }
}

// ---------------- HMMA GEMM (plain fp16, BK=32, zero per-slab addr ALU) ----------------
// Stage: [A 8KB][B 8KB]; both tiles 128 rows x 64B (32 halves), SW64 swizzle.
// MODE 1: fused x@w1 / x@w3 + SwiGLU -> g_h (CTA: 128 M x 64 N of each mat)
// MODE 2: h@w2 -> g_y                (CTA: 128 M x 128 N)
template <int MODE>
__global__ __launch_bounds__(256, 2) void hmma_gemm_kernel() {
    const int e = blockIdx.z;
    int cnt = g_counts[e];
    if (cnt > CAP) cnt = CAP;
    const int m0 = blockIdx.y * BM;
    if (m0 >= cnt) return;
    const int n0 = blockIdx.x * ((MODE == 1) ? 64 : 128);

    extern __shared__ __align__(1024) char smem[];
    uint32_t sb = smem_u32(smem);

    const int tid  = threadIdx.x;
    const int lane = tid & 31;
    const int wid  = tid >> 5;

    // ---- A cp.async: rows rA0 (0..63) and rA1 (64..127), 16B chunk (tid&3) ----
    const int rA0 = tid >> 2;
    const int rA1 = rA0 + 64;
    const int cA  = (tid & 3) * 8;      // halves
    const __half* paj[2];
    if (MODE == 1) {
        paj[0] = g_x16 + (size_t)g_tok[e * CAP + m0 + rA0] * DM + cA;
        paj[1] = g_x16 + (size_t)g_tok[e * CAP + m0 + rA1] * DM + cA;
    } else {
        paj[0] = g_h + ((size_t)e * CAP + m0 + rA0) * DH + cA;
        paj[1] = g_h + ((size_t)e * CAP + m0 + rA1) * DH + cA;
    }
    uint32_t soA[2];
    soA[0] = sb + swz64((uint32_t)(rA0 * 64 + (tid & 3) * 16));
    soA[1] = sb + swz64((uint32_t)(rA1 * 64 + (tid & 3) * 16));

    const __half* pbj[2];
    {
        int rB[2] = {rA0, rA1};
#pragma unroll
        for (int j = 0; j < 2; j++) {
            int rb = rB[j];
            if (MODE == 1) {
                if (rb < 64) pbj[j] = g_w1t + ((size_t)e * DH + n0 + rb) * DM + cA;
                else         pbj[j] = g_w3t + ((size_t)e * DH + n0 + rb - 64) * DM + cA;
            } else {
                pbj[j] = g_w2t + ((size_t)e * DM + n0 + rb) * DH + cA;
            }
        }
    }
    uint32_t soB[2];
    soB[0] = sb + 8192 + swz64((uint32_t)(rA0 * 64 + (tid & 3) * 16));
    soB[1] = sb + 8192 + swz64((uint32_t)(rA1 * 64 + (tid & 3) * 16));

    // ---- warp tiling ----
    int wm, wn, mat;
    if (MODE == 1) { wm = wid & 1; wn = (wid >> 1) & 1; mat = wid >> 2; }
    else           { wm = wid & 1; wn = wid >> 1;       mat = 0; }
    const int mbase = wm * 64;
    const int nbB   = (MODE == 1) ? (mat * 64 + wn * 32) : (wn * 32);

    const int lrow = lane & 15;
    const int lkb  = (lane & 16) ? 16 : 0;

    // ---- fully precomputed LDSM base addresses (chunk0 and chunk1 variants) ----
    uint32_t baseA[4], baseAx[4];
#pragma unroll
    for (int mi = 0; mi < 4; mi++) {
        uint32_t pre = (uint32_t)((mbase + mi * 16 + lrow) * 64 + lkb);
        baseA[mi]  = sb + swz64(pre);
        baseAx[mi] = sb + swz64(pre ^ 32u);
    }
    uint32_t baseB[2], baseBx[2];
#pragma unroll
    for (int g = 0; g < 2; g++) {
        uint32_t pre = (uint32_t)((nbB + g * 16 + lrow) * 64 + lkb);
        baseB[g]  = sb + 8192 + swz64(pre);
        baseBx[g] = sb + 8192 + swz64(pre ^ 32u);
    }

    float acc[4][4][4];
#pragma unroll
    for (int mi = 0; mi < 4; mi++)
#pragma unroll
        for (int ni = 0; ni < 4; ni++)
#pragma unroll
            for (int q = 0; q < 4; q++) acc[mi][ni][q] = 0.f;

    // ---- prologue: slabs 0..NSTAGE-2 ----
#pragma unroll
    for (int s = 0; s < NSTAGE - 1; s++) {
        uint32_t o = s * STAGE_BYTES;
        cpasync16(soA[0] + o, paj[0] + s * BK);
        cpasync16(soA[1] + o, paj[1] + s * BK);
        cpasync16(soB[0] + o, pbj[0] + s * BK);
        cpasync16(soB[1] + o, pbj[1] + s * BK);
        cp_commit();
    }
    paj[0] += (NSTAGE - 1) * BK;  paj[1] += (NSTAGE - 1) * BK;
    pbj[0] += (NSTAGE - 1) * BK;  pbj[1] += (NSTAGE - 1) * BK;

    // ---- main loop: blocks of NSTAGE slabs; stage offsets compile-time ----
    int kt = 0;
#pragma unroll 1
    for (int blk = 0; blk < KIT / NSTAGE; blk++) {
#pragma unroll
        for (int s = 0; s < NSTAGE; s++) {
            cp_wait2();
            __syncthreads();

            // prefetch slab kt+NSTAGE-1 into stage (s+NSTAGE-1)%NSTAGE
            if (kt + NSTAGE - 1 < KIT) {
                const uint32_t wo = ((s + NSTAGE - 1) & (NSTAGE - 1)) * STAGE_BYTES;
                cpasync16(soA[0] + wo, paj[0]);
                cpasync16(soA[1] + wo, paj[1]);
                cpasync16(soB[0] + wo, pbj[0]);
                cpasync16(soB[1] + wo, pbj[1]);
            }
            cp_commit();
            paj[0] += BK; paj[1] += BK; pbj[0] += BK; pbj[1] += BK;

            const uint32_t so = s * STAGE_BYTES;

            // B fragments for both k-chunks (addresses: base + imm, zero ALU)
            uint32_t bf[2][4][2];
#pragma unroll
            for (int g = 0; g < 2; g++) {
                uint32_t q0, q1, q2, q3;
                ldsm4(q0, q1, q2, q3, baseB[g] + so);
                bf[0][g * 2 + 0][0] = q0; bf[0][g * 2 + 0][1] = q2;
                bf[0][g * 2 + 1][0] = q1; bf[0][g * 2 + 1][1] = q3;
                ldsm4(q0, q1, q2, q3, baseBx[g] + so);
                bf[1][g * 2 + 0][0] = q0; bf[1][g * 2 + 0][1] = q2;
                bf[1][g * 2 + 1][0] = q1; bf[1][g * 2 + 1][1] = q3;
            }

            // per k-chunk: A fragments then 16 MMAs
#pragma unroll
            for (int c = 0; c < 2; c++) {
                uint32_t af[4][4];
#pragma unroll
                for (int mi = 0; mi < 4; mi++)
                    ldsm4(af[mi][0], af[mi][1], af[mi][2], af[mi][3],
                          (c ? baseAx[mi] : baseA[mi]) + so);
#pragma unroll
                for (int mi = 0; mi < 4; mi++)
#pragma unroll
                    for (int ni = 0; ni < 4; ni++)
                        mma16816(acc[mi][ni], af[mi], bf[c][ni]);
            }
            kt++;
        }
    }

    // ---- epilogue ----
    __syncthreads();
    if (MODE == 1) {
        float* fb = (float*)smem;   // 128 x 64 fp32 = 32KB scratch (reuse stages)
        if (mat == 1) {
#pragma unroll
            for (int mi = 0; mi < 4; mi++)
#pragma unroll
                for (int ni = 0; ni < 4; ni++) {
                    int ml = mbase + mi * 16 + (lane >> 2);
                    int nl = wn * 32 + ni * 8 + 2 * (lane & 3);
                    fb[ml * 64 + nl]           = acc[mi][ni][0];
                    fb[ml * 64 + nl + 1]       = acc[mi][ni][1];
                    fb[(ml + 8) * 64 + nl]     = acc[mi][ni][2];
                    fb[(ml + 8) * 64 + nl + 1] = acc[mi][ni][3];
                }
        }
        __syncthreads();
        if (mat == 0) {
#pragma unroll
            for (int mi = 0; mi < 4; mi++)
#pragma unroll
                for (int ni = 0; ni < 4; ni++) {
                    int ml = mbase + mi * 16 + (lane >> 2);
                    int nl = wn * 32 + ni * 8 + 2 * (lane & 3);
#pragma unroll
                    for (int hrow = 0; hrow < 2; hrow++) {
                        int mloc = ml + hrow * 8;
                        int row  = m0 + mloc;
                        if (row >= cnt) continue;
                        float a10 = acc[mi][ni][2 * hrow + 0];
                        float a11 = acc[mi][ni][2 * hrow + 1];
                        float a30 = fb[mloc * 64 + nl];
                        float a31 = fb[mloc * 64 + nl + 1];
                        float h0 = (a10 / (1.f + __expf(-a10))) * a30;
                        float h1 = (a11 / (1.f + __expf(-a11))) * a31;
                        __half2 hp = __floats2half2_rn(h0, h1);
                        size_t o = ((size_t)e * CAP + row) * DH + n0 + nl;
                        *(__half2*)(g_h + o) = hp;
                    }
                }
        }
    } else {
#pragma unroll
        for (int mi = 0; mi < 4; mi++)
#pragma unroll
            for (int ni = 0; ni < 4; ni++) {
                int ml = mbase + mi * 16 + (lane >> 2);
                int nl = nbB + ni * 8 + 2 * (lane & 3);
#pragma unroll
                for (int hrow = 0; hrow < 2; hrow++) {
                    int row = m0 + ml + hrow * 8;
                    if (row >= cnt) continue;
                    float2 v = make_float2(acc[mi][ni][2 * hrow], acc[mi][ni][2 * hrow + 1]);
                    *(float2*)(g_y + ((size_t)e * CAP + row) * DM + n0 + nl) = v;
                }
            }
    }
}

// ---------------- combine ----------------
__global__ void combine_kernel(const float* __restrict__ ew, float* __restrict__ out) {
    int i = blockIdx.x * blockDim.x + threadIdx.x;
    int n = i / (DM / 4);
    int c = (i % (DM / 4)) * 4;
    float4 r = make_float4(0.f, 0.f, 0.f, 0.f);
#pragma unroll
    for (int k = 0; k < TOPK; k++) {
        int slot = g_slot[n * TOPK + k];
        if (slot >= 0) {
            float w = ew[n * TOPK + k];
            float4 v = *(const float4*)(g_y + (size_t)slot * DM + c);
            r.x = fmaf(w, v.x, r.x);
            r.y = fmaf(w, v.y, r.y);
            r.z = fmaf(w, v.z, r.z);
            r.w = fmaf(w, v.w, r.w);
        }
    }
    *(float4*)(out + (size_t)n * DM + c) = r;
}

__global__ void counts_kernel(float* __restrict__ out_tail) {
    if (threadIdx.x < NEXP) out_tail[threadIdx.x] = (float)g_counts[threadIdx.x];
}

// ---------------- launch ----------------
extern "C" void kernel_launch(void* const* d_in, const int* in_sizes, int n_in,
                              void* d_out, int out_size) {
    const float* x  = (const float*)d_in[0];
    const float* ew = (const float*)d_in[1];
    const int*   ix = (const int*)  d_in[2];
    const float* w1 = (const float*)d_in[3];
    const float* w2 = (const float*)d_in[4];
    const float* w3 = (const float*)d_in[5];
    float* out = (float*)d_out;

    const int SMEM = NSTAGE * STAGE_BYTES;   // 65536
    cudaFuncSetAttribute(hmma_gemm_kernel<1>, cudaFuncAttributeMaxDynamicSharedMemorySize, SMEM);
    cudaFuncSetAttribute(hmma_gemm_kernel<2>, cudaFuncAttributeMaxDynamicSharedMemorySize, SMEM);

    route_kernel<<<1, 256>>>(ix);
    xcvt_kernel<<<(NTOK * DM / 4) / 256, 256>>>(x);

    dim3 wg(DH / 64, DM / 64, 3 * NEXP);     // 32 x 32 x 24
    wprep_kernel<<<wg, 256>>>(w1, w2, w3);

    dim3 g1(DH / 64, CAP / BM, NEXP);    // 32 x 20 x 8
    hmma_gemm_kernel<1><<<g1, 256, SMEM>>>();

    dim3 g2(DM / 128, CAP / BM, NEXP);   // 16 x 20 x 8
    hmma_gemm_kernel<2><<<g2, 256, SMEM>>>();

    combine_kernel<<<(NTOK * (DM / 4)) / 256, 256>>>(ew, out);

    if (out_size >= NTOK * DM + NEXP)
        counts_kernel<<<1, 32>>>(out + (size_t)NTOK * DM);
}